// round 1
// baseline (speedup 1.0000x reference)
#include <cuda_runtime.h>
#include <math.h>

#define K_CLS 128
#define D_DIM 512
#define SLICES 16          // D_DIM / 32
#define CHUNKS 9
#define WARPS 12
#define BLOCK_B (WARPS * 32)
#define ACC_PER_WARP (K_CLS * 32)   // 4096 floats = 16 KB per warp

// Scratch (device globals: no allocation allowed in kernel_launch)
__device__ float g_r[K_CLS * D_DIM];
__device__ float g_n[K_CLS];
__device__ float g_G[K_CLS * K_CLS];

// ---------------------------------------------------------------------------
// Kernel 0: zero scratch
// ---------------------------------------------------------------------------
__global__ void vmf_zero_kernel() {
    int idx = blockIdx.x * blockDim.x + threadIdx.x;
    int stride = gridDim.x * blockDim.x;
    for (int i = idx; i < K_CLS * D_DIM; i += stride) g_r[i] = 0.f;
    for (int i = idx; i < K_CLS * K_CLS; i += stride) g_G[i] = 0.f;
    if (idx < K_CLS) g_n[idx] = 0.f;
}

// ---------------------------------------------------------------------------
// Kernel 1: segment sum (per-warp privatized smem accumulators, no hot atomics)
// grid = (SLICES, CHUNKS); block handles a 32-column D-slice of a row chunk.
// ---------------------------------------------------------------------------
__device__ __forceinline__ void rmw4(float* __restrict__ acc, int l,
                                     int y0, int y1, int y2, int y3,
                                     float v0, float v1, float v2, float v3) {
    // Dedup classes within the group so the 4 smem RMW chains never alias.
    bool k1 = true, k2 = true, k3 = true;
    if (y1 == y0) { v0 += v1; k1 = false; }
    if (y2 == y0) { v0 += v2; k2 = false; }
    else if (y2 == y1) { v1 += v2; k2 = false; }
    if (y3 == y0) { v0 += v3; k3 = false; }
    else if (y3 == y1) { v1 += v3; k3 = false; }
    else if (y3 == y2) { v2 += v3; k3 = false; }
    acc[y0 * 32 + l] += v0;
    if (k1) acc[y1 * 32 + l] += v1;
    if (k2) acc[y2 * 32 + l] += v2;
    if (k3) acc[y3 * 32 + l] += v3;
}

__global__ void __launch_bounds__(BLOCK_B)
vmf_segsum_kernel(const float* __restrict__ X, const int* __restrict__ y, int N) {
    extern __shared__ float sacc[];          // WARPS * ACC_PER_WARP floats
    __shared__ int hist[K_CLS];

    const int tid = threadIdx.x;
    const int w = tid >> 5;
    const int l = tid & 31;
    const int s = blockIdx.x;                // D-slice index
    const int c = blockIdx.y;                // row chunk index
    const int colBase = s * 32 + l;

    float* acc = sacc + w * ACC_PER_WARP;
    for (int i = l; i < ACC_PER_WARP; i += 32) acc[i] = 0.f;
    if (s == 0 && tid < K_CLS) hist[tid] = 0;
    __syncthreads();

    const int RC = (N + CHUNKS - 1) / CHUNKS;
    const int rs = c * RC;
    const int re = min(N, rs + RC);

    // 16 rows per warp-iteration: front-batched loads (MLP ~16), then
    // 4 dedup'd RMW groups of 4 with independent smem chains.
    for (int base = rs + w * 16; base < re; base += WARPS * 16) {
        int   yv[16];
        float vv[16];
#pragma unroll
        for (int k = 0; k < 16; k++) {
            int r = base + k;
            bool ok = (r < re);
            yv[k] = ok ? __ldg(y + r) : -1;
            vv[k] = ok ? __ldg(X + (size_t)r * D_DIM + colBase) : 0.f;
        }
#pragma unroll
        for (int k = 1; k < 16; k++) if (yv[k] < 0) yv[k] = yv[0];  // vv is 0

#pragma unroll
        for (int g = 0; g < 4; g++)
            rmw4(acc, l, yv[g*4+0], yv[g*4+1], yv[g*4+2], yv[g*4+3],
                         vv[g*4+0], vv[g*4+1], vv[g*4+2], vv[g*4+3]);

        if (s == 0 && l == 0) {
#pragma unroll
            for (int k = 0; k < 16; k++)
                if (base + k < re) atomicAdd(&hist[yv[k]], 1);
        }
    }
    __syncthreads();

    // Reduce across the 12 warp-private buffers, flush to global once.
    for (int i = tid; i < ACC_PER_WARP; i += BLOCK_B) {
        float sum = 0.f;
#pragma unroll
        for (int w2 = 0; w2 < WARPS; w2++) sum += sacc[w2 * ACC_PER_WARP + i];
        int k = i >> 5, col = i & 31;
        atomicAdd(&g_r[k * D_DIM + s * 32 + col], sum);
    }
    if (s == 0 && tid < K_CLS) atomicAdd(&g_n[tid], (float)hist[tid]);
}

// ---------------------------------------------------------------------------
// Kernel 2: Gram matrix G = r @ r^T  (128x128x512), k-split tiled
// grid = (4, 4, 8): 32x32 output tile, 64-wide k chunk per block.
// ---------------------------------------------------------------------------
#define GT 32
#define GK 64
__global__ void __launch_bounds__(256) vmf_gram_kernel() {
    __shared__ __align__(16) float AsT[GK][GT];   // [k][i]
    __shared__ __align__(16) float BsT[GK][GT];   // [k][j]
    const int i0 = blockIdx.x * GT, j0 = blockIdx.y * GT, k0 = blockIdx.z * GK;
    const int tid = threadIdx.x;

    {
        int row = tid >> 3, q = tid & 7;   // 32 rows, 2x float4 per thread per matrix
#pragma unroll
        for (int p = 0; p < 2; p++) {
            int kq = q + p * 8;            // float4 index 0..15 (k = kq*4)
            float4 a = *(const float4*)&g_r[(size_t)(i0 + row) * D_DIM + k0 + kq * 4];
            AsT[kq*4+0][row] = a.x; AsT[kq*4+1][row] = a.y;
            AsT[kq*4+2][row] = a.z; AsT[kq*4+3][row] = a.w;
            float4 b = *(const float4*)&g_r[(size_t)(j0 + row) * D_DIM + k0 + kq * 4];
            BsT[kq*4+0][row] = b.x; BsT[kq*4+1][row] = b.y;
            BsT[kq*4+2][row] = b.z; BsT[kq*4+3][row] = b.w;
        }
    }
    __syncthreads();

    const int tx = tid & 15, ty = tid >> 4;
    float acc00 = 0.f, acc01 = 0.f, acc10 = 0.f, acc11 = 0.f;
#pragma unroll
    for (int k = 0; k < GK; k++) {
        float2 a = *(const float2*)&AsT[k][ty * 2];
        float2 b = *(const float2*)&BsT[k][tx * 2];
        acc00 += a.x * b.x; acc01 += a.x * b.y;
        acc10 += a.y * b.x; acc11 += a.y * b.y;
    }
    const int gi = i0 + ty * 2, gj = j0 + tx * 2;
    atomicAdd(&g_G[gi * K_CLS + gj],           acc00);
    atomicAdd(&g_G[gi * K_CLS + gj + 1],       acc01);
    atomicAdd(&g_G[(gi + 1) * K_CLS + gj],     acc10);
    atomicAdd(&g_G[(gi + 1) * K_CLS + gj + 1], acc11);
}

// ---------------------------------------------------------------------------
// Kernel 3: finalize — kappa / log / bessel per class, KL matrix, sum(kl^2)/K^2
// Single block, 128 threads (one per class).
// ---------------------------------------------------------------------------
__global__ void __launch_bounds__(K_CLS) vmf_finalize_kernel(float* out) {
    __shared__ float kap[K_CLS], lgk[K_CLS], bess[K_CLS], nrm[K_CLS];
    __shared__ double red[K_CLS];
    const int i = threadIdx.x;

    {
        float norm = sqrtf(g_G[i * K_CLS + i]);
        float n    = g_n[i];
        float rb   = norm / n;
        float Df   = (float)D_DIM;
        float kappa = (Df * rb - rb * rb * rb) / (1.f - rb * rb);
        if (rb > 0.9f) kappa = -0.4f + 1.39f * rb + 0.43f / (1.f - rb);
        nrm[i] = norm; kap[i] = kappa; lgk[i] = logf(kappa);

        // exponentially scaled Bessel ive(d_star, kappa) — fp32, matches
        // reference (underflows to 0 for these inputs, computed faithfully)
        const float v  = 0.5f * (float)((D_DIM & 1) ? D_DIM : D_DIM + 1) - 1.f;
        float zz = kappa / v;
        float s  = sqrtf(1.f + zz * zz);
        float t  = 1.f / s, t2 = t * t;
        float eta = s + logf(zz / (1.f + s));
        float u1 = (3.f * t - 5.f * t * t2) / 24.f;
        float u2 = (81.f * t2 - 462.f * t2 * t2 + 385.f * t2 * t2 * t2) / 1152.f;
        float u3 = (30375.f * t * t2 - 369603.f * t * t2 * t2
                    + 765765.f * t * t2 * t2 * t2
                    - 425425.f * t * t2 * t2 * t2 * t2) / 414720.f;
        float series = 1.f + u1 / v + u2 / (v * v) + u3 / (v * v * v);
        bess[i] = expf(v * eta - kappa) * series
                  / (sqrtf(2.f * (float)M_PI * v) * sqrtf(s));
    }
    __syncthreads();

    const float dstar = 0.5f * (float)((D_DIM & 1) ? D_DIM : D_DIM + 1) - 1.f;
    const float ki = kap[i], li = lgk[i], bi = bess[i], ni = nrm[i];
    double acc = 0.0;
    for (int j = 0; j < K_CLS; j++) {
        float dot = g_G[i * K_CLS + j] / (ni * nrm[j]);
        float kl  = dstar * (lgk[j] - li) - ki + bi - bess[j] + kap[j] * dot;
        acc += (double)kl * (double)kl;
    }
    red[i] = acc;
    __syncthreads();
    for (int off = 64; off > 0; off >>= 1) {
        if (i < off) red[i] += red[i + off];
        __syncthreads();
    }
    if (i == 0) out[0] = (float)(red[0] / (double)(K_CLS * K_CLS));
}

// ---------------------------------------------------------------------------
extern "C" void kernel_launch(void* const* d_in, const int* in_sizes, int n_in,
                              void* d_out, int out_size) {
    const float* X = (const float*)d_in[0];
    const int*   y = (const int*)d_in[1];
    const int    N = in_sizes[1];

    cudaFuncSetAttribute(vmf_segsum_kernel,
                         cudaFuncAttributeMaxDynamicSharedMemorySize,
                         WARPS * ACC_PER_WARP * (int)sizeof(float));

    vmf_zero_kernel<<<64, 256>>>();
    vmf_segsum_kernel<<<dim3(SLICES, CHUNKS), BLOCK_B,
                        WARPS * ACC_PER_WARP * sizeof(float)>>>(X, y, N);
    vmf_gram_kernel<<<dim3(4, 4, 8), 256>>>();
    vmf_finalize_kernel<<<1, K_CLS>>>((float*)d_out);
}

// round 2
// speedup vs baseline: 2.5760x; 2.5760x over previous
#include <cuda_runtime.h>
#include <math.h>

#define K_CLS 128
#define D_DIM 512
#define NMAX  65536
#define SORT_BLOCKS 64           // 64 blocks x 1024 threads = 65536
#define CH 12                    // row chunks per class in pass B (64 rows each)

// Scratch (device globals: no allocation allowed in kernel_launch)
__device__ float g_r[K_CLS * D_DIM];
__device__ float g_n[K_CLS];
__device__ float g_G[K_CLS * K_CLS];
__device__ int   g_H[SORT_BLOCKS * K_CLS];    // per-block histograms
__device__ int   g_base[SORT_BLOCKS * K_CLS]; // per-(block,class) scatter bases
__device__ int   g_cbase[K_CLS];              // class segment starts
__device__ int   g_cnt[K_CLS];                // class counts
__device__ int   g_perm[NMAX];                // class-sorted row indices

// ---------------------------------------------------------------------------
// Kernel 0: zero scratch
// ---------------------------------------------------------------------------
__global__ void vmf_zero_kernel() {
    int idx = blockIdx.x * blockDim.x + threadIdx.x;
    int stride = gridDim.x * blockDim.x;
    for (int i = idx; i < K_CLS * D_DIM; i += stride) g_r[i] = 0.f;
    for (int i = idx; i < K_CLS * K_CLS; i += stride) g_G[i] = 0.f;
}

// ---------------------------------------------------------------------------
// Kernel A1: per-block class histograms of y
// ---------------------------------------------------------------------------
__global__ void __launch_bounds__(1024)
vmf_hist_kernel(const int* __restrict__ y, int N) {
    __shared__ int hist[K_CLS];
    const int tid = threadIdx.x;
    if (tid < K_CLS) hist[tid] = 0;
    __syncthreads();
    int i = blockIdx.x * 1024 + tid;
    if (i < N) atomicAdd(&hist[__ldg(y + i)], 1);
    __syncthreads();
    if (tid < K_CLS) g_H[blockIdx.x * K_CLS + tid] = hist[tid];
}

// ---------------------------------------------------------------------------
// Kernel A2: scan — class bases + per-(block,class) bases + counts
// single block, 128 threads (thread k owns class k)
// ---------------------------------------------------------------------------
__global__ void __launch_bounds__(K_CLS) vmf_scan_kernel() {
    __shared__ int s[K_CLS];
    const int k = threadIdx.x;
    int cnt = 0;
#pragma unroll 4
    for (int b = 0; b < SORT_BLOCKS; b++) cnt += g_H[b * K_CLS + k];
    g_cnt[k] = cnt;
    g_n[k] = (float)cnt;
    s[k] = cnt;
    __syncthreads();
    // Hillis–Steele inclusive scan over 128 entries
    for (int off = 1; off < K_CLS; off <<= 1) {
        int v = (k >= off) ? s[k - off] : 0;
        __syncthreads();
        s[k] += v;
        __syncthreads();
    }
    int base = s[k] - cnt;          // exclusive
    g_cbase[k] = base;
    int run = base;
    for (int b = 0; b < SORT_BLOCKS; b++) {
        g_base[b * K_CLS + k] = run;
        run += g_H[b * K_CLS + k];
    }
}

// ---------------------------------------------------------------------------
// Kernel A3: scatter rows into class-sorted perm (warp-aggregated atomics)
// ---------------------------------------------------------------------------
__global__ void __launch_bounds__(1024)
vmf_scatter_kernel(const int* __restrict__ y, int N) {
    __shared__ int cur[K_CLS];
    const int tid = threadIdx.x;
    if (tid < K_CLS) cur[tid] = g_base[blockIdx.x * K_CLS + tid];
    __syncthreads();
    int i = blockIdx.x * 1024 + tid;
    if (i < N) {
        int cls = __ldg(y + i);
        unsigned mask = __match_any_sync(__activemask(), cls);
        int leader = __ffs(mask) - 1;
        int rank = __popc(mask & ((1u << (tid & 31)) - 1));
        int pos = 0;
        if ((tid & 31) == leader) pos = atomicAdd(&cur[cls], __popc(mask));
        pos = __shfl_sync(mask, pos, leader);
        g_perm[pos + rank] = i;
    }
}

// ---------------------------------------------------------------------------
// Kernel B: gather segment sum. grid=(CH, K_CLS), block=128 threads.
// Thread t accumulates float4 columns [4t, 4t+4) over a 64-row chunk of its class.
// ---------------------------------------------------------------------------
__global__ void __launch_bounds__(128)
vmf_segsum_kernel(const float* __restrict__ X) {
    const int t = threadIdx.x;
    const int chunk = blockIdx.x;
    const int cls = blockIdx.y;
    const int count = g_cnt[cls];
    const int s0 = chunk * 64;
    if (s0 >= count) return;
    int cnt = count - s0;
    if (chunk < CH - 1) cnt = min(cnt, 64);

    const int* __restrict__ p = g_perm + g_cbase[cls] + s0;
    const float4* __restrict__ X4 = (const float4*)X;   // row stride: 128 float4

    float4 acc = make_float4(0.f, 0.f, 0.f, 0.f);
    int r = 0;
    for (; r + 8 <= cnt; r += 8) {
        int rows[8];
#pragma unroll
        for (int u = 0; u < 8; u++) rows[u] = __ldg(p + r + u);
        float4 v[8];
#pragma unroll
        for (int u = 0; u < 8; u++)
            v[u] = __ldg(X4 + (size_t)rows[u] * (D_DIM / 4) + t);
#pragma unroll
        for (int u = 0; u < 8; u++) {
            acc.x += v[u].x; acc.y += v[u].y;
            acc.z += v[u].z; acc.w += v[u].w;
        }
    }
    for (; r < cnt; r++) {
        int row = __ldg(p + r);
        float4 v = __ldg(X4 + (size_t)row * (D_DIM / 4) + t);
        acc.x += v.x; acc.y += v.y; acc.z += v.z; acc.w += v.w;
    }
    float* dst = &g_r[cls * D_DIM + t * 4];
    atomicAdd(dst + 0, acc.x);
    atomicAdd(dst + 1, acc.y);
    atomicAdd(dst + 2, acc.z);
    atomicAdd(dst + 3, acc.w);
}

// ---------------------------------------------------------------------------
// Kernel 2: Gram matrix G = r @ r^T  (128x128x512), k-split tiled
// ---------------------------------------------------------------------------
#define GT 32
#define GK 64
__global__ void __launch_bounds__(256) vmf_gram_kernel() {
    __shared__ __align__(16) float AsT[GK][GT];
    __shared__ __align__(16) float BsT[GK][GT];
    const int i0 = blockIdx.x * GT, j0 = blockIdx.y * GT, k0 = blockIdx.z * GK;
    const int tid = threadIdx.x;
    {
        int row = tid >> 3, q = tid & 7;
#pragma unroll
        for (int pp = 0; pp < 2; pp++) {
            int kq = q + pp * 8;
            float4 a = *(const float4*)&g_r[(size_t)(i0 + row) * D_DIM + k0 + kq * 4];
            AsT[kq*4+0][row] = a.x; AsT[kq*4+1][row] = a.y;
            AsT[kq*4+2][row] = a.z; AsT[kq*4+3][row] = a.w;
            float4 b = *(const float4*)&g_r[(size_t)(j0 + row) * D_DIM + k0 + kq * 4];
            BsT[kq*4+0][row] = b.x; BsT[kq*4+1][row] = b.y;
            BsT[kq*4+2][row] = b.z; BsT[kq*4+3][row] = b.w;
        }
    }
    __syncthreads();
    const int tx = tid & 15, ty = tid >> 4;
    float acc00 = 0.f, acc01 = 0.f, acc10 = 0.f, acc11 = 0.f;
#pragma unroll
    for (int k = 0; k < GK; k++) {
        float2 a = *(const float2*)&AsT[k][ty * 2];
        float2 b = *(const float2*)&BsT[k][tx * 2];
        acc00 += a.x * b.x; acc01 += a.x * b.y;
        acc10 += a.y * b.x; acc11 += a.y * b.y;
    }
    const int gi = i0 + ty * 2, gj = j0 + tx * 2;
    atomicAdd(&g_G[gi * K_CLS + gj],           acc00);
    atomicAdd(&g_G[gi * K_CLS + gj + 1],       acc01);
    atomicAdd(&g_G[(gi + 1) * K_CLS + gj],     acc10);
    atomicAdd(&g_G[(gi + 1) * K_CLS + gj + 1], acc11);
}

// ---------------------------------------------------------------------------
// Kernel 3: finalize — parallel over pairs. 1 block, 256 threads.
// ---------------------------------------------------------------------------
__global__ void __launch_bounds__(256) vmf_finalize_kernel(float* out) {
    __shared__ float kap[K_CLS], lgk[K_CLS], bess[K_CLS], inv_nrm[K_CLS];
    __shared__ double red[256];
    const int tid = threadIdx.x;

    if (tid < K_CLS) {
        const int i = tid;
        float norm = sqrtf(g_G[i * K_CLS + i]);
        float n    = g_n[i];
        float rb   = norm / n;
        float Df   = (float)D_DIM;
        float kappa = (Df * rb - rb * rb * rb) / (1.f - rb * rb);
        if (rb > 0.9f) kappa = -0.4f + 1.39f * rb + 0.43f / (1.f - rb);
        inv_nrm[i] = 1.f / norm; kap[i] = kappa; lgk[i] = logf(kappa);

        // exponentially scaled Bessel ive(d_star, kappa), fp32 (matches ref)
        const float v  = 0.5f * (float)((D_DIM & 1) ? D_DIM : D_DIM + 1) - 1.f;
        float zz = kappa / v;
        float s  = sqrtf(1.f + zz * zz);
        float t  = 1.f / s, t2 = t * t;
        float eta = s + logf(zz / (1.f + s));
        float u1 = (3.f * t - 5.f * t * t2) / 24.f;
        float u2 = (81.f * t2 - 462.f * t2 * t2 + 385.f * t2 * t2 * t2) / 1152.f;
        float u3 = (30375.f * t * t2 - 369603.f * t * t2 * t2
                    + 765765.f * t * t2 * t2 * t2
                    - 425425.f * t * t2 * t2 * t2 * t2) / 414720.f;
        float series = 1.f + u1 / v + u2 / (v * v) + u3 / (v * v * v);
        bess[i] = expf(v * eta - kappa) * series
                  / (sqrtf(2.f * (float)M_PI * v) * sqrtf(s));
    }
    __syncthreads();

    const float dstar = 0.5f * (float)((D_DIM & 1) ? D_DIM : D_DIM + 1) - 1.f;
    double a0 = 0.0, a1 = 0.0, a2 = 0.0, a3 = 0.0;
    // 16384 pairs / 256 threads = 64 per thread, 4 independent chains
    for (int q = 0; q < 64; q += 4) {
#pragma unroll
        for (int u = 0; u < 4; u++) {
            int pair = tid * 64 + q + u;
            int i = pair >> 7, j = pair & 127;
            float dot = g_G[i * K_CLS + j] * inv_nrm[i] * inv_nrm[j];
            float kl  = dstar * (lgk[j] - lgk[i]) - kap[i] + bess[i] - bess[j]
                        + kap[j] * dot;
            double d = (double)kl * (double)kl;
            if (u == 0) a0 += d; else if (u == 1) a1 += d;
            else if (u == 2) a2 += d; else a3 += d;
        }
    }
    red[tid] = (a0 + a1) + (a2 + a3);
    __syncthreads();
    for (int off = 128; off > 0; off >>= 1) {
        if (tid < off) red[tid] += red[tid + off];
        __syncthreads();
    }
    if (tid == 0) out[0] = (float)(red[0] / (double)(K_CLS * K_CLS));
}

// ---------------------------------------------------------------------------
extern "C" void kernel_launch(void* const* d_in, const int* in_sizes, int n_in,
                              void* d_out, int out_size) {
    const float* X = (const float*)d_in[0];
    const int*   y = (const int*)d_in[1];
    const int    N = in_sizes[1];

    vmf_zero_kernel<<<64, 256>>>();
    vmf_hist_kernel<<<SORT_BLOCKS, 1024>>>(y, N);
    vmf_scan_kernel<<<1, K_CLS>>>();
    vmf_scatter_kernel<<<SORT_BLOCKS, 1024>>>(y, N);
    vmf_segsum_kernel<<<dim3(CH, K_CLS), 128>>>(X);
    vmf_gram_kernel<<<dim3(4, 4, 8), 256>>>();
    vmf_finalize_kernel<<<1, 256>>>((float*)d_out);
}